// round 14
// baseline (speedup 1.0000x reference)
#include <cuda_runtime.h>
#include <stdint.h>

// HashGridEncoder: instant-NGP multiresolution hash grid encode.
// x: [N,3] f32; aabb: [3] f32; table: [16, 2^19, 2] f32. out: [N,32] f32.
// Levels 0..2 dense (res 16/32/64), 3..15 hashed.
// R14: R10 (best: paired v4 gathers, 136 regs) with the FULL 32-wide
// transpose tile and a single store phase: one continuous 16-level gather
// stream per warp, no mid-kernel drain/refill bubble. Half-tile only
// existed for occupancy at regs=32 (obsolete at 136 regs / 3 blocks).

#define HG_TABLE_SIZE (1u << 19)
#define HG_MASK (HG_TABLE_SIZE - 1u)
#define HG_PRIME_Y 2654435761u
#define HG_PRIME_Z 805459861u

// ---------------- dense levels (0..2): branchless paired loads -------------
struct DenseSetup {
    unsigned addrA, addrB;   // even-aligned pair base indices (v4 targets)
    unsigned oX, oY;         // odd pairs' first corner indices (v2 targets)
    unsigned e;              // 1 if base is even
    float tx, ty, tz;
};

__device__ __forceinline__ void dense_setup(
    int l, float xn0, float xn1, float xn2, DenseSetup& s)
{
    const unsigned res = 16u << l;
    const float resf = (float)res;
    const float px = xn0 * resf, py = xn1 * resf, pz = xn2 * resf;
    const float fx = floorf(px), fy = floorf(py), fz = floorf(pz);
    s.tx = px - fx; s.ty = py - fy; s.tz = pz - fz;
    const unsigned cx = (unsigned)fx, cy = (unsigned)fy, cz = (unsigned)fz;
    const unsigned st = res + 1;          // odd
    const unsigned s2 = st * st;          // odd
    const unsigned base = cx + cy * st + cz * s2;
    const unsigned e = (base & 1u) ^ 1u;  // 1 if base even
    s.e = e;
    // pairs: P0=base(p) P1=base+st(~p) P2=base+s2(~p) P3=base+st+s2(p)
    s.addrA = e ? base           : base + st;      // even pair (P0 or P1)
    s.addrB = e ? base + st + s2 : base + s2;      // even pair (P3 or P2)
    s.oX    = e ? base + st      : base;           // odd pair  (P1 or P0)
    s.oY    = e ? base + s2      : base + st + s2; // odd pair  (P2 or P3)
}

struct DenseVals {
    float ax0, ay0, ax1, ay1;   // v4 A
    float bx0, by0, bx1, by1;   // v4 B
    float Xx0, Xy0, Xx1, Xy1;   // v2 pair X (oX, oX+1)
    float Yx0, Yy0, Yx1, Yy1;   // v2 pair Y (oY, oY+1)
};

__device__ __forceinline__ void dense_issue(
    const float2* __restrict__ tl, const DenseSetup& s, DenseVals& v)
{
    asm volatile("ld.global.nc.v4.f32 {%0, %1, %2, %3}, [%4];"
                 : "=f"(v.ax0), "=f"(v.ay0), "=f"(v.ax1), "=f"(v.ay1)
                 : "l"(tl + s.addrA));
    asm volatile("ld.global.nc.v4.f32 {%0, %1, %2, %3}, [%4];"
                 : "=f"(v.bx0), "=f"(v.by0), "=f"(v.bx1), "=f"(v.by1)
                 : "l"(tl + s.addrB));
    asm volatile("ld.global.nc.v2.f32 {%0, %1}, [%2];"
                 : "=f"(v.Xx0), "=f"(v.Xy0) : "l"(tl + s.oX));
    asm volatile("ld.global.nc.v2.f32 {%0, %1}, [%2];"
                 : "=f"(v.Xx1), "=f"(v.Xy1) : "l"(tl + s.oX + 1));
    asm volatile("ld.global.nc.v2.f32 {%0, %1}, [%2];"
                 : "=f"(v.Yx0), "=f"(v.Yy0) : "l"(tl + s.oY));
    asm volatile("ld.global.nc.v2.f32 {%0, %1}, [%2];"
                 : "=f"(v.Yx1), "=f"(v.Yy1) : "l"(tl + s.oY + 1));
}

__device__ __forceinline__ void dense_reduce(
    const DenseSetup& s, const DenseVals& v, float& f0, float& f1)
{
    const bool e = s.e != 0;
    // P0 (000,100): e ? A : X ; P1 (010,110): e ? X : A
    // P2 (001,101): e ? Y : B ; P3 (011,111): e ? B : Y
    const float c000x = e ? v.ax0 : v.Xx0, c000y = e ? v.ay0 : v.Xy0;
    const float c100x = e ? v.ax1 : v.Xx1, c100y = e ? v.ay1 : v.Xy1;
    const float c010x = e ? v.Xx0 : v.ax0, c010y = e ? v.Xy0 : v.ay0;
    const float c110x = e ? v.Xx1 : v.ax1, c110y = e ? v.Xy1 : v.ay1;
    const float c001x = e ? v.Yx0 : v.bx0, c001y = e ? v.Yy0 : v.by0;
    const float c101x = e ? v.Yx1 : v.bx1, c101y = e ? v.Yy1 : v.by1;
    const float c011x = e ? v.bx0 : v.Yx0, c011y = e ? v.by0 : v.Yy0;
    const float c111x = e ? v.bx1 : v.Yx1, c111y = e ? v.by1 : v.Yy1;

    const float wx1 = s.tx, wx0 = 1.0f - s.tx;
    const float wy1 = s.ty, wy0 = 1.0f - s.ty;
    const float wz1 = s.tz, wz0 = 1.0f - s.tz;
    const float w00 = wy0 * wz0, w10 = wy1 * wz0;
    const float w01 = wy0 * wz1, w11 = wy1 * wz1;
    const float w000 = wx0 * w00, w100 = wx1 * w00;
    const float w010 = wx0 * w10, w110 = wx1 * w10;
    const float w001 = wx0 * w01, w101 = wx1 * w01;
    const float w011 = wx0 * w11, w111 = wx1 * w11;

    f0 = w000 * c000x + w100 * c100x + w010 * c010x + w110 * c110x +
         w001 * c001x + w101 * c101x + w011 * c011x + w111 * c111x;
    f1 = w000 * c000y + w100 * c100y + w010 * c010y + w110 * c110y +
         w001 * c001y + w101 * c101y + w011 * c011y + w111 * c111y;
}

// ---------------- hashed levels (3..15) ----------------
struct HashSetup {
    unsigned q[8];
    float tx, ty, tz;
    unsigned even;        // 1 if cx even -> x-pairs are aligned {q&~1, q|1}
};

__device__ __forceinline__ void hash_setup(
    int l, float xn0, float xn1, float xn2, HashSetup& s)
{
    const unsigned res = 16u << l;
    const float resf = (float)res;
    const float px = xn0 * resf, py = xn1 * resf, pz = xn2 * resf;
    const float fx = floorf(px), fy = floorf(py), fz = floorf(pz);
    s.tx = px - fx; s.ty = py - fy; s.tz = pz - fz;
    const unsigned cx = (unsigned)fx, cy = (unsigned)fy, cz = (unsigned)fz;

    const unsigned hy0 = cy * HG_PRIME_Y, hy1 = hy0 + HG_PRIME_Y;
    const unsigned hz0 = cz * HG_PRIME_Z, hz1 = hz0 + HG_PRIME_Z;
    const unsigned e00 = hy0 ^ hz0, e10 = hy1 ^ hz0;
    const unsigned e01 = hy0 ^ hz1, e11 = hy1 ^ hz1;
    const unsigned cx1 = cx + 1u;
    s.q[0] = (cx  ^ e00) & HG_MASK;  s.q[1] = (cx1 ^ e00) & HG_MASK;
    s.q[2] = (cx  ^ e10) & HG_MASK;  s.q[3] = (cx1 ^ e10) & HG_MASK;
    s.q[4] = (cx  ^ e01) & HG_MASK;  s.q[5] = (cx1 ^ e01) & HG_MASK;
    s.q[6] = (cx  ^ e11) & HG_MASK;  s.q[7] = (cx1 ^ e11) & HG_MASK;
    s.even = (cx & 1u) ^ 1u;
}

__device__ __forceinline__ void hash_issue(
    const float2* __restrict__ tl, const HashSetup& s,
    float vx[8], float vy[8])
{
    if (s.even) {
#pragma unroll
        for (int p = 0; p < 4; ++p) {
            const unsigned qa = s.q[2 * p] & ~1u;
            asm volatile("ld.global.nc.v4.f32 {%0, %1, %2, %3}, [%4];"
                         : "=f"(vx[2 * p]), "=f"(vy[2 * p]),
                           "=f"(vx[2 * p + 1]), "=f"(vy[2 * p + 1])
                         : "l"(tl + qa));
        }
    } else {
#pragma unroll
        for (int j = 0; j < 8; ++j) {
            asm volatile("ld.global.nc.v2.f32 {%0, %1}, [%2];"
                         : "=f"(vx[j]), "=f"(vy[j])
                         : "l"(tl + s.q[j]));
        }
    }
}

__device__ __forceinline__ void hash_reduce(
    const HashSetup& s, const float vx[8], const float vy[8],
    float& f0, float& f1)
{
    float x0f0[4], x0f1[4], x1f0[4], x1f1[4];
#pragma unroll
    for (int p = 0; p < 4; ++p) {
        const bool sw = s.even && (s.q[2 * p] & 1u);
        x0f0[p] = sw ? vx[2 * p + 1] : vx[2 * p];
        x0f1[p] = sw ? vy[2 * p + 1] : vy[2 * p];
        x1f0[p] = sw ? vx[2 * p]     : vx[2 * p + 1];
        x1f1[p] = sw ? vy[2 * p]     : vy[2 * p + 1];
    }

    const float wx1 = s.tx, wx0 = 1.0f - s.tx;
    const float wy1 = s.ty, wy0 = 1.0f - s.ty;
    const float wz1 = s.tz, wz0 = 1.0f - s.tz;
    const float w00 = wy0 * wz0, w10 = wy1 * wz0;
    const float w01 = wy0 * wz1, w11 = wy1 * wz1;
    const float w000 = wx0 * w00, w100 = wx1 * w00;
    const float w010 = wx0 * w10, w110 = wx1 * w10;
    const float w001 = wx0 * w01, w101 = wx1 * w01;
    const float w011 = wx0 * w11, w111 = wx1 * w11;

    f0 = w000 * x0f0[0] + w100 * x1f0[0] + w010 * x0f0[1] + w110 * x1f0[1] +
         w001 * x0f0[2] + w101 * x1f0[2] + w011 * x0f0[3] + w111 * x1f0[3];
    f1 = w000 * x0f1[0] + w100 * x1f1[0] + w010 * x0f1[1] + w110 * x1f1[1] +
         w001 * x0f1[2] + w101 * x1f1[2] + w011 * x0f1[3] + w111 * x1f1[3];
}

// ---- batch: dense levels 0..2 (cols 0..5) ----
__device__ __forceinline__ void batch_dense3(
    const float2* __restrict__ tab,
    float xn0, float xn1, float xn2, float* __restrict__ sline)
{
    DenseSetup s[3];
    dense_setup(0, xn0, xn1, xn2, s[0]);
    dense_setup(1, xn0, xn1, xn2, s[1]);
    dense_setup(2, xn0, xn1, xn2, s[2]);

    DenseVals v[3];
#pragma unroll
    for (int i = 0; i < 3; ++i)
        dense_issue(tab + (size_t)i * HG_TABLE_SIZE, s[i], v[i]);

#pragma unroll
    for (int i = 0; i < 3; ++i) {
        float f0, f1;
        dense_reduce(s[i], v[i], f0, f1);
        sline[2 * i]     = f0;
        sline[2 * i + 1] = f1;
    }
}

// ---- batch: CNT hashed levels L0.. (cols 2*L0..) ----
template <int L0, int CNT>
__device__ __forceinline__ void batch_hashed(
    const float2* __restrict__ tab,
    float xn0, float xn1, float xn2,
    float* __restrict__ sline)
{
    HashSetup s[CNT];
#pragma unroll
    for (int i = 0; i < CNT; ++i)
        hash_setup(L0 + i, xn0, xn1, xn2, s[i]);

    float vx[CNT][8], vy[CNT][8];
#pragma unroll
    for (int i = 0; i < CNT; ++i)
        hash_issue(tab + (size_t)(L0 + i) * HG_TABLE_SIZE, s[i], vx[i], vy[i]);

#pragma unroll
    for (int i = 0; i < CNT; ++i) {
        float f0, f1;
        hash_reduce(s[i], vx[i], vy[i], f0, f1);
        sline[2 * (L0 + i)]     = f0;
        sline[2 * (L0 + i) + 1] = f1;
    }
}

__global__ __launch_bounds__(128) void hashgrid_encode_kernel(
    const float* __restrict__ x,
    const float* __restrict__ aabb,
    const float* __restrict__ table,
    float* __restrict__ out,
    int n)
{
    // per-warp FULL tile: 32 points x 32 feats, padded -> conflict-free
    __shared__ float sbuf[4][32][33];

    const int tid  = blockIdx.x * blockDim.x + threadIdx.x;
    const int warp = threadIdx.x >> 5;
    const int lane = threadIdx.x & 31;
    const bool active = (tid < n);
    const int pi = active ? tid : 0;   // clamp so gathers stay in-bounds

    const float a0 = __ldg(aabb + 0);
    const float a1 = __ldg(aabb + 1);
    const float a2 = __ldg(aabb + 2);

    const float px_in = __ldg(x + 3 * (size_t)pi + 0);
    const float py_in = __ldg(x + 3 * (size_t)pi + 1);
    const float pz_in = __ldg(x + 3 * (size_t)pi + 2);

    // normalize_aabb then bound (-1,1) -> [0,1]; matches reference fp32 order
    const float xn0 = (px_in / a0 + 1.0f) * 0.5f;
    const float xn1 = (py_in / a1 + 1.0f) * 0.5f;
    const float xn2 = (pz_in / a2 + 1.0f) * 0.5f;

    const float2* __restrict__ tab = (const float2*)table;
    float* sline = &sbuf[warp][lane][0];
    const int base_pt = blockIdx.x * blockDim.x + warp * 32;

    // one continuous 16-level gather stream, R10 batch sizes
    batch_dense3(tab, xn0, xn1, xn2, sline);           // levels 0..2
    batch_hashed<3, 3>(tab, xn0, xn1, xn2, sline);     // levels 3..5
    batch_hashed<6, 2>(tab, xn0, xn1, xn2, sline);     // levels 6..7
    batch_hashed<8, 3>(tab, xn0, xn1, xn2, sline);     // levels 8..10
    batch_hashed<11, 3>(tab, xn0, xn1, xn2, sline);    // levels 11..13
    batch_hashed<14, 2>(tab, xn0, xn1, xn2, sline);    // levels 14..15

    __syncwarp();

    // single coalesced transposed store: 32 contiguous 128B rows per warp
#pragma unroll
    for (int r = 0; r < 32; ++r) {
        const int pt = base_pt + r;
        if (pt < n) {
            out[(size_t)pt * 32 + lane] = sbuf[warp][r][lane];
        }
    }
}

extern "C" void kernel_launch(void* const* d_in, const int* in_sizes, int n_in,
                              void* d_out, int out_size) {
    const float* x     = (const float*)d_in[0];   // [N,3]
    const float* aabb  = (const float*)d_in[1];   // [3]
    const float* table = (const float*)d_in[2];   // [16, 2^19, 2]
    float* out = (float*)d_out;                   // [N, 32]

    const int n = in_sizes[0] / 3;
    const int threads = 128;
    const int blocks = (n + threads - 1) / threads;
    hashgrid_encode_kernel<<<blocks, threads>>>(x, aabb, table, out, n);
}

// round 16
// speedup vs baseline: 1.7536x; 1.7536x over previous
#include <cuda_runtime.h>
#include <stdint.h>

// HashGridEncoder: instant-NGP multiresolution hash grid encode.
// x: [N,3] f32; aabb: [3] f32; table: [16, 2^19, 2] f32. out: [N,32] f32.
// Levels 0..2 dense (res 16/32/64), 3..15 hashed.
// R16 = R15 resubmitted (R15 hit a transient "device busy" infra error and
// never ran): exact R10 (best, 540us: paired v4 gathers, two half-tile
// phases, 136 regs) + st.global.cs streaming output stores so the 256MB
// output stream doesn't evict the L2-resident 67MB table.

#define HG_TABLE_SIZE (1u << 19)
#define HG_MASK (HG_TABLE_SIZE - 1u)
#define HG_PRIME_Y 2654435761u
#define HG_PRIME_Z 805459861u

// ---------------- dense levels (0..2): branchless paired loads -------------
struct DenseSetup {
    unsigned addrA, addrB;   // even-aligned pair base indices (v4 targets)
    unsigned oX, oY;         // odd pairs' first corner indices (v2 targets)
    unsigned e;              // 1 if base is even
    float tx, ty, tz;
};

__device__ __forceinline__ void dense_setup(
    int l, float xn0, float xn1, float xn2, DenseSetup& s)
{
    const unsigned res = 16u << l;
    const float resf = (float)res;
    const float px = xn0 * resf, py = xn1 * resf, pz = xn2 * resf;
    const float fx = floorf(px), fy = floorf(py), fz = floorf(pz);
    s.tx = px - fx; s.ty = py - fy; s.tz = pz - fz;
    const unsigned cx = (unsigned)fx, cy = (unsigned)fy, cz = (unsigned)fz;
    const unsigned st = res + 1;          // odd
    const unsigned s2 = st * st;          // odd
    const unsigned base = cx + cy * st + cz * s2;
    const unsigned e = (base & 1u) ^ 1u;  // 1 if base even
    s.e = e;
    // pairs: P0=base(p) P1=base+st(~p) P2=base+s2(~p) P3=base+st+s2(p)
    s.addrA = e ? base           : base + st;      // even pair (P0 or P1)
    s.addrB = e ? base + st + s2 : base + s2;      // even pair (P3 or P2)
    s.oX    = e ? base + st      : base;           // odd pair  (P1 or P0)
    s.oY    = e ? base + s2      : base + st + s2; // odd pair  (P2 or P3)
}

struct DenseVals {
    float ax0, ay0, ax1, ay1;   // v4 A: slot0 (f0,f1), slot1 (f0,f1)
    float bx0, by0, bx1, by1;   // v4 B
    float Xx0, Xy0, Xx1, Xy1;   // v2 pair X (oX, oX+1)
    float Yx0, Yy0, Yx1, Yy1;   // v2 pair Y (oY, oY+1)
};

__device__ __forceinline__ void dense_issue(
    const float2* __restrict__ tl, const DenseSetup& s, DenseVals& v)
{
    asm volatile("ld.global.nc.v4.f32 {%0, %1, %2, %3}, [%4];"
                 : "=f"(v.ax0), "=f"(v.ay0), "=f"(v.ax1), "=f"(v.ay1)
                 : "l"(tl + s.addrA));
    asm volatile("ld.global.nc.v4.f32 {%0, %1, %2, %3}, [%4];"
                 : "=f"(v.bx0), "=f"(v.by0), "=f"(v.bx1), "=f"(v.by1)
                 : "l"(tl + s.addrB));
    asm volatile("ld.global.nc.v2.f32 {%0, %1}, [%2];"
                 : "=f"(v.Xx0), "=f"(v.Xy0) : "l"(tl + s.oX));
    asm volatile("ld.global.nc.v2.f32 {%0, %1}, [%2];"
                 : "=f"(v.Xx1), "=f"(v.Xy1) : "l"(tl + s.oX + 1));
    asm volatile("ld.global.nc.v2.f32 {%0, %1}, [%2];"
                 : "=f"(v.Yx0), "=f"(v.Yy0) : "l"(tl + s.oY));
    asm volatile("ld.global.nc.v2.f32 {%0, %1}, [%2];"
                 : "=f"(v.Yx1), "=f"(v.Yy1) : "l"(tl + s.oY + 1));
}

__device__ __forceinline__ void dense_reduce(
    const DenseSetup& s, const DenseVals& v, float& f0, float& f1)
{
    const bool e = s.e != 0;
    // P0 (000,100): e ? A : X ; P1 (010,110): e ? X : A
    // P2 (001,101): e ? Y : B ; P3 (011,111): e ? B : Y
    const float c000x = e ? v.ax0 : v.Xx0, c000y = e ? v.ay0 : v.Xy0;
    const float c100x = e ? v.ax1 : v.Xx1, c100y = e ? v.ay1 : v.Xy1;
    const float c010x = e ? v.Xx0 : v.ax0, c010y = e ? v.Xy0 : v.ay0;
    const float c110x = e ? v.Xx1 : v.ax1, c110y = e ? v.Xy1 : v.ay1;
    const float c001x = e ? v.Yx0 : v.bx0, c001y = e ? v.Yy0 : v.by0;
    const float c101x = e ? v.Yx1 : v.bx1, c101y = e ? v.Yy1 : v.by1;
    const float c011x = e ? v.bx0 : v.Yx0, c011y = e ? v.by0 : v.Yy0;
    const float c111x = e ? v.bx1 : v.Yx1, c111y = e ? v.by1 : v.Yy1;

    const float wx1 = s.tx, wx0 = 1.0f - s.tx;
    const float wy1 = s.ty, wy0 = 1.0f - s.ty;
    const float wz1 = s.tz, wz0 = 1.0f - s.tz;
    const float w00 = wy0 * wz0, w10 = wy1 * wz0;
    const float w01 = wy0 * wz1, w11 = wy1 * wz1;
    const float w000 = wx0 * w00, w100 = wx1 * w00;
    const float w010 = wx0 * w10, w110 = wx1 * w10;
    const float w001 = wx0 * w01, w101 = wx1 * w01;
    const float w011 = wx0 * w11, w111 = wx1 * w11;

    f0 = w000 * c000x + w100 * c100x + w010 * c010x + w110 * c110x +
         w001 * c001x + w101 * c101x + w011 * c011x + w111 * c111x;
    f1 = w000 * c000y + w100 * c100y + w010 * c010y + w110 * c110y +
         w001 * c001y + w101 * c101y + w011 * c011y + w111 * c111y;
}

// ---------------- hashed levels (3..15) ----------------
struct HashSetup {
    unsigned q[8];
    float tx, ty, tz;
    unsigned even;        // 1 if cx even -> x-pairs are aligned {q&~1, q|1}
};

__device__ __forceinline__ void hash_setup(
    int l, float xn0, float xn1, float xn2, HashSetup& s)
{
    const unsigned res = 16u << l;
    const float resf = (float)res;
    const float px = xn0 * resf, py = xn1 * resf, pz = xn2 * resf;
    const float fx = floorf(px), fy = floorf(py), fz = floorf(pz);
    s.tx = px - fx; s.ty = py - fy; s.tz = pz - fz;
    const unsigned cx = (unsigned)fx, cy = (unsigned)fy, cz = (unsigned)fz;

    const unsigned hy0 = cy * HG_PRIME_Y, hy1 = hy0 + HG_PRIME_Y;
    const unsigned hz0 = cz * HG_PRIME_Z, hz1 = hz0 + HG_PRIME_Z;
    const unsigned e00 = hy0 ^ hz0, e10 = hy1 ^ hz0;
    const unsigned e01 = hy0 ^ hz1, e11 = hy1 ^ hz1;
    const unsigned cx1 = cx + 1u;
    s.q[0] = (cx  ^ e00) & HG_MASK;  s.q[1] = (cx1 ^ e00) & HG_MASK;
    s.q[2] = (cx  ^ e10) & HG_MASK;  s.q[3] = (cx1 ^ e10) & HG_MASK;
    s.q[4] = (cx  ^ e01) & HG_MASK;  s.q[5] = (cx1 ^ e01) & HG_MASK;
    s.q[6] = (cx  ^ e11) & HG_MASK;  s.q[7] = (cx1 ^ e11) & HG_MASK;
    s.even = (cx & 1u) ^ 1u;
}

__device__ __forceinline__ void hash_issue(
    const float2* __restrict__ tl, const HashSetup& s,
    float vx[8], float vy[8])
{
    if (s.even) {
#pragma unroll
        for (int p = 0; p < 4; ++p) {
            const unsigned qa = s.q[2 * p] & ~1u;
            asm volatile("ld.global.nc.v4.f32 {%0, %1, %2, %3}, [%4];"
                         : "=f"(vx[2 * p]), "=f"(vy[2 * p]),
                           "=f"(vx[2 * p + 1]), "=f"(vy[2 * p + 1])
                         : "l"(tl + qa));
        }
    } else {
#pragma unroll
        for (int j = 0; j < 8; ++j) {
            asm volatile("ld.global.nc.v2.f32 {%0, %1}, [%2];"
                         : "=f"(vx[j]), "=f"(vy[j])
                         : "l"(tl + s.q[j]));
        }
    }
}

__device__ __forceinline__ void hash_reduce(
    const HashSetup& s, const float vx[8], const float vy[8],
    float& f0, float& f1)
{
    float x0f0[4], x0f1[4], x1f0[4], x1f1[4];
#pragma unroll
    for (int p = 0; p < 4; ++p) {
        const bool sw = s.even && (s.q[2 * p] & 1u);
        x0f0[p] = sw ? vx[2 * p + 1] : vx[2 * p];
        x0f1[p] = sw ? vy[2 * p + 1] : vy[2 * p];
        x1f0[p] = sw ? vx[2 * p]     : vx[2 * p + 1];
        x1f1[p] = sw ? vy[2 * p]     : vy[2 * p + 1];
    }

    const float wx1 = s.tx, wx0 = 1.0f - s.tx;
    const float wy1 = s.ty, wy0 = 1.0f - s.ty;
    const float wz1 = s.tz, wz0 = 1.0f - s.tz;
    const float w00 = wy0 * wz0, w10 = wy1 * wz0;
    const float w01 = wy0 * wz1, w11 = wy1 * wz1;
    const float w000 = wx0 * w00, w100 = wx1 * w00;
    const float w010 = wx0 * w10, w110 = wx1 * w10;
    const float w001 = wx0 * w01, w101 = wx1 * w01;
    const float w011 = wx0 * w11, w111 = wx1 * w11;

    f0 = w000 * x0f0[0] + w100 * x1f0[0] + w010 * x0f0[1] + w110 * x1f0[1] +
         w001 * x0f0[2] + w101 * x1f0[2] + w011 * x0f0[3] + w111 * x1f0[3];
    f1 = w000 * x0f1[0] + w100 * x1f1[0] + w010 * x0f1[1] + w110 * x1f1[1] +
         w001 * x0f1[2] + w101 * x1f1[2] + w011 * x0f1[3] + w111 * x1f1[3];
}

// ---- batch: dense levels 0..2 (cols 0..5) ----
__device__ __forceinline__ void batch_dense3(
    const float2* __restrict__ tab,
    float xn0, float xn1, float xn2, float* __restrict__ sline)
{
    DenseSetup s[3];
    dense_setup(0, xn0, xn1, xn2, s[0]);
    dense_setup(1, xn0, xn1, xn2, s[1]);
    dense_setup(2, xn0, xn1, xn2, s[2]);

    DenseVals v[3];
#pragma unroll
    for (int i = 0; i < 3; ++i)
        dense_issue(tab + (size_t)i * HG_TABLE_SIZE, s[i], v[i]);

#pragma unroll
    for (int i = 0; i < 3; ++i) {
        float f0, f1;
        dense_reduce(s[i], v[i], f0, f1);
        sline[2 * i]     = f0;
        sline[2 * i + 1] = f1;
    }
}

// ---- batch: CNT hashed levels L0.. (cols colbase..) ----
template <int L0, int CNT>
__device__ __forceinline__ void batch_hashed(
    const float2* __restrict__ tab,
    float xn0, float xn1, float xn2,
    float* __restrict__ sline, int colbase)
{
    HashSetup s[CNT];
#pragma unroll
    for (int i = 0; i < CNT; ++i)
        hash_setup(L0 + i, xn0, xn1, xn2, s[i]);

    float vx[CNT][8], vy[CNT][8];
#pragma unroll
    for (int i = 0; i < CNT; ++i)
        hash_issue(tab + (size_t)(L0 + i) * HG_TABLE_SIZE, s[i], vx[i], vy[i]);

#pragma unroll
    for (int i = 0; i < CNT; ++i) {
        float f0, f1;
        hash_reduce(s[i], vx[i], vy[i], f0, f1);
        sline[colbase + 2 * i]     = f0;
        sline[colbase + 2 * i + 1] = f1;
    }
}

__global__ __launch_bounds__(128) void hashgrid_encode_kernel(
    const float* __restrict__ x,
    const float* __restrict__ aabb,
    const float* __restrict__ table,
    float* __restrict__ out,
    int n)
{
    // per-warp HALF tile: 32 points x 16 feats (levels 0-7, reused for 8-15)
    __shared__ float sbuf[4][32][17];

    const int tid  = blockIdx.x * blockDim.x + threadIdx.x;
    const int warp = threadIdx.x >> 5;
    const int lane = threadIdx.x & 31;
    const bool active = (tid < n);
    const int pi = active ? tid : 0;   // clamp so gathers stay in-bounds

    const float a0 = __ldg(aabb + 0);
    const float a1 = __ldg(aabb + 1);
    const float a2 = __ldg(aabb + 2);

    const float px_in = __ldg(x + 3 * (size_t)pi + 0);
    const float py_in = __ldg(x + 3 * (size_t)pi + 1);
    const float pz_in = __ldg(x + 3 * (size_t)pi + 2);

    // normalize_aabb then bound (-1,1) -> [0,1]; matches reference fp32 order
    const float xn0 = (px_in / a0 + 1.0f) * 0.5f;
    const float xn1 = (py_in / a1 + 1.0f) * 0.5f;
    const float xn2 = (pz_in / a2 + 1.0f) * 0.5f;

    const float2* __restrict__ tab = (const float2*)table;
    float* sline = &sbuf[warp][lane][0];
    const int base_pt = blockIdx.x * blockDim.x + warp * 32;

    // ---- half 0: levels 0..7 ----
    batch_dense3(tab, xn0, xn1, xn2, sline);               // cols 0..5
    batch_hashed<3, 3>(tab, xn0, xn1, xn2, sline, 6);      // cols 6..11
    batch_hashed<6, 2>(tab, xn0, xn1, xn2, sline, 12);     // cols 12..15
    __syncwarp();
#pragma unroll
    for (int rr = 0; rr < 16; ++rr) {
        const int r = 2 * rr + (lane >> 4);
        const int c = lane & 15;
        const int pt = base_pt + r;
        if (pt < n) {
            asm volatile("st.global.cs.f32 [%0], %1;"
                         :: "l"(out + (size_t)pt * 32 + c),
                            "f"(sbuf[warp][r][c]) : "memory");
        }
    }
    __syncwarp();

    // ---- half 1: levels 8..15 ----
    batch_hashed<8, 3>(tab, xn0, xn1, xn2, sline, 0);      // cols 0..5
    batch_hashed<11, 3>(tab, xn0, xn1, xn2, sline, 6);     // cols 6..11
    batch_hashed<14, 2>(tab, xn0, xn1, xn2, sline, 12);    // cols 12..15
    __syncwarp();
#pragma unroll
    for (int rr = 0; rr < 16; ++rr) {
        const int r = 2 * rr + (lane >> 4);
        const int c = lane & 15;
        const int pt = base_pt + r;
        if (pt < n) {
            asm volatile("st.global.cs.f32 [%0], %1;"
                         :: "l"(out + (size_t)pt * 32 + 16 + c),
                            "f"(sbuf[warp][r][c]) : "memory");
        }
    }
}

extern "C" void kernel_launch(void* const* d_in, const int* in_sizes, int n_in,
                              void* d_out, int out_size) {
    const float* x     = (const float*)d_in[0];   // [N,3]
    const float* aabb  = (const float*)d_in[1];   // [3]
    const float* table = (const float*)d_in[2];   // [16, 2^19, 2]
    float* out = (float*)d_out;                   // [N, 32]

    const int n = in_sizes[0] / 3;
    const int threads = 128;
    const int blocks = (n + threads - 1) / threads;
    hashgrid_encode_kernel<<<blocks, threads>>>(x, aabb, table, out, n);
}